// round 9
// baseline (speedup 1.0000x reference)
#include <cuda_runtime.h>
#include <cuda_bf16.h>
#include <cstdint>

// ---------------- problem constants ----------------
#define B_     16
#define L_     8192
#define IN_    57
#define DM     64
#define DS     32
#define HD     32
#define NH     4
#define DI     128          // EXP*DM
#define DPROJ  324          // 2*DI + 2*DS + NH
#define NL     2
#define OUT_   6
#define Q      64           // chunk length
#define NCH    (L_ / Q)     // 128 chunks
#define NSEG   16           // scan segments
#define CPS    (NCH / NSEG) // 8 chunks per segment
#define BL     (B_ * L_)    // 131072 rows

// ---------------- scratch (device globals; allocation-free) ----------------
__device__ float g_h [BL * DM];
__device__ float g_X [BL * DI];
__device__ float g_Z [BL * DI];
__device__ float g_y [BL * DI];
__device__ float g_Bm[BL * DS];
__device__ float g_Cm[BL * DS];
__device__ float g_dt[BL * NH];
__device__ float g_la[BL * NH];
__device__ float g_Sd[B_ * NH * NCH * HD * DS];    // chunk delta states
__device__ float g_h0[B_ * NH * NCH * HD * DS];    // segment-local entry states
__device__ float g_aQ[B_ * NH * NCH];              // chunk total decay
__device__ float g_segS[B_ * NH * NSEG * HD * DS]; // segment delta states
__device__ float g_segA[B_ * NH * NSEG];           // segment decay product
__device__ float g_segIn[B_ * NH * NSEG * HD * DS];// segment entry states
__device__ double g_pool[B_ * 16 * DM];

// ---------------- helpers ----------------
__device__ __forceinline__ float siluf(float v) { return v / (1.f + __expf(-v)); }
__device__ __forceinline__ float softplusf(float v) { return (v > 20.f) ? v : log1pf(__expf(v)); }

__device__ __forceinline__ unsigned pk_bf2(float a, float b) {
    __nv_bfloat162 t = __floats2bfloat162_rn(a, b);   // a -> low half (k), b -> high half (k+1)
    return *reinterpret_cast<unsigned*>(&t);
}
// split (v0,v1) pair into packed bf16 hi and lo words
__device__ __forceinline__ void pack_hilo(float v0, float v1, unsigned& uhi, unsigned& ulo) {
    float h0 = __bfloat162float(__float2bfloat16_rn(v0));
    float h1 = __bfloat162float(__float2bfloat16_rn(v1));
    uhi = pk_bf2(h0, h1);
    ulo = pk_bf2(v0 - h0, v1 - h1);
}
__device__ __forceinline__ void mma_bf16(float* d, const unsigned* a, const unsigned* b) {
    asm volatile("mma.sync.aligned.m16n8k16.row.col.f32.bf16.bf16.f32 "
                 "{%0,%1,%2,%3},{%4,%5,%6,%7},{%8,%9},{%0,%1,%2,%3};"
                 : "+f"(d[0]), "+f"(d[1]), "+f"(d[2]), "+f"(d[3])
                 : "r"(a[0]), "r"(a[1]), "r"(a[2]), "r"(a[3]),
                   "r"(b[0]), "r"(b[1]));
}

// ================= K1: linear_in  h = x @ W_in + b_in =================
__global__ void k_linear_in(const float* __restrict__ x,
                            const float* __restrict__ W,
                            const float* __restrict__ bias) {
    const int row0 = blockIdx.x * 16;
    __shared__ float sx[16][IN_ + 1];
    const int tid = threadIdx.x;
    for (int idx = tid; idx < 16 * IN_; idx += 256) {
        int r = idx / IN_, k = idx % IN_;
        sx[r][k] = x[(size_t)(row0 + r) * IN_ + k];
    }
    __syncthreads();
    const int c = tid & 63, q = tid >> 6;
    float bc = bias[c];
    float acc[4] = {bc, bc, bc, bc};
    for (int k = 0; k < IN_; k++) {
        float wv = __ldg(&W[k * DM + c]);
#pragma unroll
        for (int j = 0; j < 4; j++) acc[j] += sx[q * 4 + j][k] * wv;
    }
#pragma unroll
    for (int j = 0; j < 4; j++)
        g_h[(size_t)(row0 + q * 4 + j) * DM + c] = acc[j];
}

// ================= K2: in_proj via bf16x3 MMA (packed hi/lo cached) =====
#define IPM 128
#define PH_ST 36     // packed h [r][32 pairs]; 36 ≡ 4 mod 32 -> conflict-free frags
#define PW_ST 36     // packed W^T [n][32 pairs]
#define IP_SMEM ((2 * IPM * PH_ST + 2 * 64 * PW_ST + 384) * 4)

__device__ __forceinline__ void ip_store(int row, int c, float v0, float v1,
                                         const float* __restrict__ dtb) {
    size_t r = (size_t)row;
    if (c < DI) {
        *reinterpret_cast<float2*>(&g_Z[r * DI + c]) = make_float2(siluf(v0), siluf(v1));
    } else if (c < 2 * DI) {
        *reinterpret_cast<float2*>(&g_X[r * DI + (c - DI)]) = make_float2(siluf(v0), siluf(v1));
    } else if (c < 2 * DI + DS) {
        *reinterpret_cast<float2*>(&g_Bm[r * DS + (c - 2 * DI)]) = make_float2(siluf(v0), siluf(v1));
    } else if (c < 2 * DI + 2 * DS) {
        *reinterpret_cast<float2*>(&g_Cm[r * DS + (c - 2 * DI - DS)]) = make_float2(siluf(v0), siluf(v1));
    } else {
        int hh = c - (2 * DI + 2 * DS);
        *reinterpret_cast<float2*>(&g_dt[r * NH + hh]) =
            make_float2(softplusf(v0 + __ldg(&dtb[hh])), softplusf(v1 + __ldg(&dtb[hh + 1])));
    }
}

__global__ void k_inproj_mma(const float* __restrict__ W,
                             const float* __restrict__ bias,
                             const float* __restrict__ dt_bias,
                             int l) {
    extern __shared__ unsigned ism[];
    unsigned* uHhi = ism;
    unsigned* uHlo = uHhi + IPM * PH_ST;
    unsigned* uWhi = uHlo + IPM * PH_ST;
    unsigned* uWlo = uWhi + 64 * PW_ST;
    float* sBias = reinterpret_cast<float*>(uWlo + 64 * PW_ST);

    const int row0 = blockIdx.x * IPM;
    const int tid = threadIdx.x;
    const int w = tid >> 5, lane = tid & 31;
    const int g = lane >> 2, tq = lane & 3;
    const float* Wl = W + (size_t)l * DM * DPROJ;
    const float* dtb = dt_bias + l * NH;

    for (int idx = tid; idx < IPM * 32; idx += 256) {
        int r = idx >> 5, kp = idx & 31;
        float2 v = *reinterpret_cast<const float2*>(&g_h[(size_t)(row0 + r) * DM + 2 * kp]);
        pack_hilo(v.x, v.y, uHhi[r * PH_ST + kp], uHlo[r * PH_ST + kp]);
    }
    for (int idx = tid; idx < 384; idx += 256)
        sBias[idx] = (idx < DPROJ) ? bias[l * DPROJ + idx] : 0.f;
    __syncthreads();

    const int rA0 = (w * 16 + g) * PH_ST;
    const int rA1 = (w * 16 + g + 8) * PH_ST;

    for (int chunk = 0; chunk < 6; chunk++) {
        for (int idx = tid; idx < 64 * 32; idx += 256) {
            int kp = idx >> 6, n = idx & 63;
            int c = chunk * 64 + n;
            float v0 = 0.f, v1 = 0.f;
            if (c < DPROJ) {
                v0 = __ldg(&Wl[(size_t)(2 * kp) * DPROJ + c]);
                v1 = __ldg(&Wl[(size_t)(2 * kp + 1) * DPROJ + c]);
            }
            pack_hilo(v0, v1, uWhi[n * PW_ST + kp], uWlo[n * PW_ST + kp]);
        }
        __syncthreads();

        float fa[8][4];
#pragma unroll
        for (int nt = 0; nt < 8; nt++)
#pragma unroll
            for (int j = 0; j < 4; j++) fa[nt][j] = 0.f;

#pragma unroll
        for (int kp0 = 0; kp0 < 32; kp0 += 8) {   // K = 16 per iter
            unsigned ahi[4], alo[4];
            ahi[0] = uHhi[rA0 + kp0 + tq];     alo[0] = uHlo[rA0 + kp0 + tq];
            ahi[1] = uHhi[rA1 + kp0 + tq];     alo[1] = uHlo[rA1 + kp0 + tq];
            ahi[2] = uHhi[rA0 + kp0 + tq + 4]; alo[2] = uHlo[rA0 + kp0 + tq + 4];
            ahi[3] = uHhi[rA1 + kp0 + tq + 4]; alo[3] = uHlo[rA1 + kp0 + tq + 4];
#pragma unroll
            for (int nt = 0; nt < 8; nt++) {
                const int bo0 = (nt * 8 + g) * PW_ST + kp0 + tq;
                unsigned bhi[2] = {uWhi[bo0], uWhi[bo0 + 4]};
                unsigned blo[2] = {uWlo[bo0], uWlo[bo0 + 4]};
                mma_bf16(fa[nt], ahi, bhi);
                mma_bf16(fa[nt], ahi, blo);
                mma_bf16(fa[nt], alo, bhi);
            }
        }
        __syncthreads();

#pragma unroll
        for (int nt = 0; nt < 8; nt++) {
            int cg = chunk * 64 + nt * 8 + 2 * tq;
            if (cg >= DPROJ) continue;
            float b0v = sBias[cg], b1v = sBias[cg + 1];
            int r0 = row0 + w * 16 + g;
            ip_store(r0,     cg, fa[nt][0] + b0v, fa[nt][1] + b1v, dtb);
            ip_store(r0 + 8, cg, fa[nt][2] + b0v, fa[nt][3] + b1v, dtb);
        }
    }
}

// ================= K3: per-chunk summary (Sdelta, aQ, la) =================
#define CS_STRIDE 34
__global__ void k_chunk_summary(const float* __restrict__ A_log, int l) {
    const int bx = blockIdx.x;
    const int ch = bx & (NCH - 1);
    const int h  = (bx >> 7) & 3;
    const int b  = bx >> 9;
    const size_t base = (size_t)b * L_ + (size_t)ch * Q;
    __shared__ __align__(8) float sX[Q * CS_STRIDE];
    __shared__ __align__(8) float sB[Q * CS_STRIDE];
    __shared__ float sla[Q], sw_[Q], sdt[Q];
    const int tid = threadIdx.x;               // 256 threads

    for (int idx = tid; idx < Q * 32; idx += 256) {
        int s = idx >> 5, j = idx & 31;
        sX[s * CS_STRIDE + j] = g_X [(base + s) * DI + h * HD + j];
        sB[s * CS_STRIDE + j] = g_Bm[(base + s) * DS + j];
    }
    if (tid < Q) sdt[tid] = g_dt[(base + tid) * NH + h];
    __syncthreads();

    const float A = -expf(A_log[l * NH + h]);
    if (tid < Q) {
        float v = sdt[tid] * A;
#pragma unroll
        for (int o = 1; o < 32; o <<= 1) {
            float u = __shfl_up_sync(0xffffffffu, v, o);
            if ((tid & 31) >= o) v += u;
        }
        sla[tid] = v;
    }
    __syncthreads();
    if (tid >= 32 && tid < 64) sla[tid] += sla[31];
    __syncthreads();
    const float laQ = sla[Q - 1];
    if (tid < Q) {
        g_la[(base + tid) * NH + h] = sla[tid];
        sw_[tid] = sdt[tid] * __expf(laQ - sla[tid]);
    }
    __syncthreads();
    for (int idx = tid; idx < Q * HD; idx += 256) {
        int s = idx >> 5;
        sX[s * CS_STRIDE + (idx & 31)] *= sw_[s];
    }
    __syncthreads();

    const int p0 = (tid >> 4) * 2, n0 = (tid & 15) * 2;
    float a00 = 0.f, a01 = 0.f, a10 = 0.f, a11 = 0.f;
#pragma unroll 8
    for (int s = 0; s < Q; s++) {
        float2 xv = *reinterpret_cast<const float2*>(&sX[s * CS_STRIDE + p0]);
        float2 bv = *reinterpret_cast<const float2*>(&sB[s * CS_STRIDE + n0]);
        a00 += xv.x * bv.x; a01 += xv.x * bv.y;
        a10 += xv.y * bv.x; a11 += xv.y * bv.y;
    }
    float* dst = &g_Sd[(size_t)bx * 1024];
    *reinterpret_cast<float2*>(&dst[p0 * 32 + n0])       = make_float2(a00, a01);
    *reinterpret_cast<float2*>(&dst[(p0 + 1) * 32 + n0]) = make_float2(a10, a11);
    if (tid == 0) g_aQ[bx] = __expf(laQ);
}

// ================= K4a: segment-local scan =================
__global__ void k_scan_seg() {
    const int blk = blockIdx.x;
    const int bh = blk >> 4, seg = blk & (NSEG - 1);
    const int tid = threadIdx.x;       // 1024
    const size_t cbase = (size_t)bh * NCH + seg * CPS;
    float hloc = 0.f;
#pragma unroll
    for (int j = 0; j < CPS; j++) {
        size_t o = (cbase + j) * 1024 + tid;
        g_h0[o] = hloc;
        hloc = __ldg(&g_aQ[cbase + j]) * hloc + g_Sd[o];
    }
    g_segS[(size_t)blk * 1024 + tid] = hloc;
    if (tid == 0) {
        float p = 1.f;
#pragma unroll
        for (int j = 0; j < CPS; j++) p *= g_aQ[cbase + j];
        g_segA[blk] = p;
    }
}

// ================= K4b: top-level segment scan =================
__global__ void k_scan_top() {
    const int bh = blockIdx.x;         // 64 blocks
    const int tid = threadIdx.x;       // 1024
    float carry = 0.f;
#pragma unroll
    for (int seg = 0; seg < NSEG; seg++) {
        size_t o = ((size_t)bh * NSEG + seg) * 1024 + tid;
        g_segIn[o] = carry;
        carry = __ldg(&g_segA[bh * NSEG + seg]) * carry + g_segS[o];
    }
}

// ================= K5: chunk output via bf16x3 MMA =================
#define SXO 40    // sX float row stride
#define PB_ST 20  // packed [row][16 pairs] (B, C, h0)   20 ≡ 4*5 mod 32
#define PG_ST 36  // packed G [t][32 pairs]
#define PXT_ST 36 // packed X^T [p][32 pairs]
#define CO_SMEM ((Q*SXO + 2*HD*PXT_ST + 4*Q*PB_ST + 2*HD*PB_ST + 2*Q*PG_ST + 3*Q) * 4)

__global__ void k_chunk_output_mma(const float* __restrict__ Dp, int l) {
    extern __shared__ float sm[];
    float* sX = sm;                                          // [64][SXO]
    unsigned* uXThi = reinterpret_cast<unsigned*>(sX + Q * SXO);  // [32][PXT_ST]
    unsigned* uXTlo = uXThi + HD * PXT_ST;
    unsigned* uBhi  = uXTlo + HD * PXT_ST;                   // [64][PB_ST]
    unsigned* uBlo  = uBhi + Q * PB_ST;
    unsigned* uChi  = uBlo + Q * PB_ST;                      // [64][PB_ST]
    unsigned* uClo  = uChi + Q * PB_ST;
    unsigned* uHhi  = uClo + Q * PB_ST;                      // [32][PB_ST]
    unsigned* uHlo  = uHhi + HD * PB_ST;
    unsigned* uGhi  = uHlo + HD * PB_ST;                     // [64][PG_ST]
    unsigned* uGlo  = uGhi + Q * PG_ST;
    float* sla = reinterpret_cast<float*>(uGlo + Q * PG_ST);
    float* sdt = sla + Q;
    float* sE  = sdt + Q;
    __shared__ float sprefA;

    const int bx = blockIdx.x;
    const int ch = bx & (NCH - 1);
    const int h  = (bx >> 7) & 3;
    const int b  = bx >> 9;
    const int bhIdx = b * NH + h;
    const size_t base = (size_t)b * L_ + (size_t)ch * Q;
    const int tid = threadIdx.x;         // 256
    const int w = tid >> 5, lane = tid & 31;
    const int g = lane >> 2, tq = lane & 3;
    const int mrow = (w & 3) * 16;

    if (tid == 0) {
        float p = 1.f;
        int j0 = ch & (CPS - 1);
        size_t cb = (size_t)bhIdx * NCH + (size_t)(ch & ~(CPS - 1));
        for (int j = 0; j < j0; j++) p *= g_aQ[cb + j];
        sprefA = p;
    }
    // sX float (epilogue use)
    for (int idx = tid; idx < Q * 32; idx += 256) {
        int s = idx >> 5, j = idx & 31;
        sX[s * SXO + j] = g_X[(base + s) * DI + h * HD + j];
    }
    // B, C packed (pairs along n, contiguous in gmem)
    for (int idx = tid; idx < Q * 16; idx += 256) {
        int s = idx >> 4, np = idx & 15;
        float2 bv = *reinterpret_cast<const float2*>(&g_Bm[(base + s) * DS + 2 * np]);
        pack_hilo(bv.x, bv.y, uBhi[s * PB_ST + np], uBlo[s * PB_ST + np]);
        float2 cv = *reinterpret_cast<const float2*>(&g_Cm[(base + s) * DS + 2 * np]);
        pack_hilo(cv.x, cv.y, uChi[s * PB_ST + np], uClo[s * PB_ST + np]);
    }
    // X^T packed (pairs along s)
    for (int idx = tid; idx < HD * 32; idx += 256) {
        int p = idx & 31, sp = idx >> 5;
        float x0 = g_X[(base + 2 * sp)     * DI + h * HD + p];
        float x1 = g_X[(base + 2 * sp + 1) * DI + h * HD + p];
        pack_hilo(x0, x1, uXThi[p * PXT_ST + sp], uXTlo[p * PXT_ST + sp]);
    }
    if (tid < Q) {
        float la = g_la[(base + tid) * NH + h];
        sla[tid] = la;
        sdt[tid] = g_dt[(base + tid) * NH + h];
        sE[tid] = __expf(la);
    }
    __syncthreads();

    // combined entry state -> packed (pairs along n)
    {
        const float pa = sprefA;
        const int seg = ch >> 3;
        const size_t sio = ((size_t)bhIdx * NSEG + seg) * 1024;
        for (int idx = tid; idx < HD * 16; idx += 256) {
            int p = idx >> 4, np = idx & 15;
            float2 a = *reinterpret_cast<const float2*>(&g_h0[(size_t)bx * 1024 + p * 32 + 2 * np]);
            float2 si = *reinterpret_cast<const float2*>(&g_segIn[sio + p * 32 + 2 * np]);
            pack_hilo(a.x + pa * si.x, a.y + pa * si.y,
                      uHhi[p * PB_ST + np], uHlo[p * PB_ST + np]);
        }
    }
    __syncthreads();

    // ---- Phase 1: G = C . B^T  (M=64 t, N=64 s, K=32 n -> 2 bf16 iters) ----
    const int shalf = (w >> 2) * 32;
    float ga[4][4];
#pragma unroll
    for (int nt = 0; nt < 4; nt++)
#pragma unroll
        for (int j = 0; j < 4; j++) ga[nt][j] = 0.f;

#pragma unroll
    for (int kp0 = 0; kp0 < 16; kp0 += 8) {
        unsigned ahi[4], alo[4];
        const int a0 = (mrow + g) * PB_ST + kp0 + tq;
        const int a1 = (mrow + g + 8) * PB_ST + kp0 + tq;
        ahi[0] = uChi[a0];     alo[0] = uClo[a0];
        ahi[1] = uChi[a1];     alo[1] = uClo[a1];
        ahi[2] = uChi[a0 + 4]; alo[2] = uClo[a0 + 4];
        ahi[3] = uChi[a1 + 4]; alo[3] = uClo[a1 + 4];
#pragma unroll
        for (int nt = 0; nt < 4; nt++) {
            const int bo = (shalf + nt * 8 + g) * PB_ST + kp0 + tq;
            unsigned bhi[2] = {uBhi[bo], uBhi[bo + 4]};
            unsigned blo[2] = {uBlo[bo], uBlo[bo + 4]};
            mma_bf16(ga[nt], ahi, bhi);
            mma_bf16(ga[nt], ahi, blo);
            mma_bf16(ga[nt], alo, bhi);
        }
    }

    // ---- Phase 2: mask+exp G -> packed uG (no sync needed before: distinct arrays) ----
#pragma unroll
    for (int nt = 0; nt < 4; nt++) {
        int s0 = shalf + nt * 8 + 2 * tq;
        int sp = s0 >> 1;
        int t0 = mrow + g, t1 = t0 + 8;
        float la0 = sla[t0], la1 = sla[t1];
        float d0 = sdt[s0], d1 = sdt[s0 + 1];
        float ls0 = sla[s0], ls1 = sla[s0 + 1];
        float g00 = (s0 <= t0)     ? ga[nt][0] * d0 * __expf(la0 - ls0) : 0.f;
        float g01 = (s0 + 1 <= t0) ? ga[nt][1] * d1 * __expf(la0 - ls1) : 0.f;
        float g10 = (s0 <= t1)     ? ga[nt][2] * d0 * __expf(la1 - ls0) : 0.f;
        float g11 = (s0 + 1 <= t1) ? ga[nt][3] * d1 * __expf(la1 - ls1) : 0.f;
        pack_hilo(g00, g01, uGhi[t0 * PG_ST + sp], uGlo[t0 * PG_ST + sp]);
        pack_hilo(g10, g11, uGhi[t1 * PG_ST + sp], uGlo[t1 * PG_ST + sp]);
    }
    __syncthreads();

    // ---- Phase 3: fa = G.X (K=64), fb = C.h0^T (K=32); Y = fa + E(t)*fb ----
    const int phalf = (w >> 2) * 16;
    float fa[2][4], fb[2][4];
#pragma unroll
    for (int nt = 0; nt < 2; nt++)
#pragma unroll
        for (int j = 0; j < 4; j++) { fa[nt][j] = 0.f; fb[nt][j] = 0.f; }

#pragma unroll
    for (int kp0 = 0; kp0 < 32; kp0 += 8) {
        unsigned ahi[4], alo[4];
        const int a0 = (mrow + g) * PG_ST + kp0 + tq;
        const int a1 = (mrow + g + 8) * PG_ST + kp0 + tq;
        ahi[0] = uGhi[a0];     alo[0] = uGlo[a0];
        ahi[1] = uGhi[a1];     alo[1] = uGlo[a1];
        ahi[2] = uGhi[a0 + 4]; alo[2] = uGlo[a0 + 4];
        ahi[3] = uGhi[a1 + 4]; alo[3] = uGlo[a1 + 4];
#pragma unroll
        for (int nt = 0; nt < 2; nt++) {
            const int bo = (phalf + nt * 8 + g) * PXT_ST + kp0 + tq;
            unsigned bhi[2] = {uXThi[bo], uXThi[bo + 4]};
            unsigned blo[2] = {uXTlo[bo], uXTlo[bo + 4]};
            mma_bf16(fa[nt], ahi, bhi);
            mma_bf16(fa[nt], ahi, blo);
            mma_bf16(fa[nt], alo, bhi);
        }
    }
#pragma unroll
    for (int kp0 = 0; kp0 < 16; kp0 += 8) {
        unsigned ahi[4], alo[4];
        const int a0 = (mrow + g) * PB_ST + kp0 + tq;
        const int a1 = (mrow + g + 8) * PB_ST + kp0 + tq;
        ahi[0] = uChi[a0];     alo[0] = uClo[a0];
        ahi[1] = uChi[a1];     alo[1] = uClo[a1];
        ahi[2] = uChi[a0 + 4]; alo[2] = uClo[a0 + 4];
        ahi[3] = uChi[a1 + 4]; alo[3] = uClo[a1 + 4];
#pragma unroll
        for (int nt = 0; nt < 2; nt++) {
            const int bo = (phalf + nt * 8 + g) * PB_ST + kp0 + tq;
            unsigned bhi[2] = {uHhi[bo], uHhi[bo + 4]};
            unsigned blo[2] = {uHlo[bo], uHlo[bo + 4]};
            mma_bf16(fb[nt], ahi, bhi);
            mma_bf16(fb[nt], ahi, blo);
            mma_bf16(fb[nt], alo, bhi);
        }
    }

    // ---- Epilogue: Y = fa + E(t)*fb + D*X, gated by Z ----
    const float Dh = Dp[l * NH + h];
    const float E0 = sE[mrow + g], E1 = sE[mrow + g + 8];
#pragma unroll
    for (int nt = 0; nt < 2; nt++) {
        int pc = phalf + nt * 8 + 2 * tq;
        {
            int t = mrow + g;
            size_t o = (base + t) * DI + h * HD + pc;
            float2 z = *reinterpret_cast<const float2*>(&g_Z[o]);
            float2 r;
            r.x = (fa[nt][0] + E0 * fb[nt][0] + Dh * sX[t * SXO + pc]) * z.x;
            r.y = (fa[nt][1] + E0 * fb[nt][1] + Dh * sX[t * SXO + pc + 1]) * z.y;
            *reinterpret_cast<float2*>(&g_y[o]) = r;
        }
        {
            int t = mrow + g + 8;
            size_t o = (base + t) * DI + h * HD + pc;
            float2 z = *reinterpret_cast<const float2*>(&g_Z[o]);
            float2 r;
            r.x = (fa[nt][2] + E1 * fb[nt][2] + Dh * sX[t * SXO + pc]) * z.x;
            r.y = (fa[nt][3] + E1 * fb[nt][3] + Dh * sX[t * SXO + pc + 1]) * z.y;
            *reinterpret_cast<float2*>(&g_y[o]) = r;
        }
    }
}

// ================= K6: out_proj via bf16x3 MMA + residual =================
#define OPM 64
#define PY_ST 68    // packed y [r][64 pairs]; 68 ≡ 4 mod 32
#define PWO_ST 68   // packed W^T [n][64 pairs]
#define OP_SMEM ((2 * OPM * PY_ST + 2 * 64 * PWO_ST + 64) * 4)
__global__ void k_outproj_mma(const float* __restrict__ Wo,
                              const float* __restrict__ bo,
                              int l) {
    extern __shared__ unsigned osm[];
    unsigned* uYhi = osm;
    unsigned* uYlo = uYhi + OPM * PY_ST;
    unsigned* uWhi = uYlo + OPM * PY_ST;
    unsigned* uWlo = uWhi + 64 * PWO_ST;
    float* sB2 = reinterpret_cast<float*>(uWlo + 64 * PWO_ST);

    const int row0 = blockIdx.x * OPM;
    const int tid = threadIdx.x;
    const int w = tid >> 5, lane = tid & 31;
    const int g = lane >> 2, tq = lane & 3;
    const int mrow = (w & 3) * 16;
    const int nhalf = (w >> 2) * 32;
    const float* Wl = Wo + (size_t)l * DI * DM;

    for (int idx = tid; idx < OPM * 64; idx += 256) {
        int r = idx >> 6, kp = idx & 63;
        float2 v = *reinterpret_cast<const float2*>(&g_y[(size_t)(row0 + r) * DI + 2 * kp]);
        pack_hilo(v.x, v.y, uYhi[r * PY_ST + kp], uYlo[r * PY_ST + kp]);
    }
    for (int idx = tid; idx < 64 * 64; idx += 256) {
        int kp = idx >> 6, n = idx & 63;
        float v0 = __ldg(&Wl[(size_t)(2 * kp) * DM + n]);
        float v1 = __ldg(&Wl[(size_t)(2 * kp + 1) * DM + n]);
        pack_hilo(v0, v1, uWhi[n * PWO_ST + kp], uWlo[n * PWO_ST + kp]);
    }
    if (tid < 64) sB2[tid] = bo[l * DM + tid];
    __syncthreads();

    const int rA0 = (mrow + g) * PY_ST;
    const int rA1 = (mrow + g + 8) * PY_ST;

    float fa[4][4];
#pragma unroll
    for (int nt = 0; nt < 4; nt++)
#pragma unroll
        for (int j = 0; j < 4; j++) fa[nt][j] = 0.f;

#pragma unroll
    for (int kp0 = 0; kp0 < 64; kp0 += 8) {   // K = 16 per iter, total 128
        unsigned ahi[4], alo[4];
        ahi[0] = uYhi[rA0 + kp0 + tq];     alo[0] = uYlo[rA0 + kp0 + tq];
        ahi[1] = uYhi[rA1 + kp0 + tq];     alo[1] = uYlo[rA1 + kp0 + tq];
        ahi[2] = uYhi[rA0 + kp0 + tq + 4]; alo[2] = uYlo[rA0 + kp0 + tq + 4];
        ahi[3] = uYhi[rA1 + kp0 + tq + 4]; alo[3] = uYlo[rA1 + kp0 + tq + 4];
#pragma unroll
        for (int nt = 0; nt < 4; nt++) {
            const int bo = (nhalf + nt * 8 + g) * PWO_ST + kp0 + tq;
            unsigned bhi[2] = {uWhi[bo], uWhi[bo + 4]};
            unsigned blo[2] = {uWlo[bo], uWlo[bo + 4]};
            mma_bf16(fa[nt], ahi, bhi);
            mma_bf16(fa[nt], ahi, blo);
            mma_bf16(fa[nt], alo, bhi);
        }
    }

#pragma unroll
    for (int nt = 0; nt < 4; nt++) {
        int c = nhalf + nt * 8 + 2 * tq;
        float bc0 = sB2[c], bc1 = sB2[c + 1];
#pragma unroll
        for (int half = 0; half < 2; half++) {
            int r = row0 + mrow + g + half * 8;
            size_t o = (size_t)r * DM + c;
            float2 hv = *reinterpret_cast<float2*>(&g_h[o]);
            hv.x += fa[nt][half * 2 + 0] + bc0;
            hv.y += fa[nt][half * 2 + 1] + bc1;
            *reinterpret_cast<float2*>(&g_h[o]) = hv;
        }
    }
}

// ================= K7a: pooling partial sums =================
__global__ void k_pool_a() {
    const int b = blockIdx.x >> 4, seg = blockIdx.x & 15;
    const int tid = threadIdx.x;   // 256
    const int d = tid & 63, part = tid >> 6;
    double s = 0.0;
    for (int ll = seg * 512 + part; ll < (seg + 1) * 512; ll += 4)
        s += (double)g_h[((size_t)b * L_ + ll) * DM + d];
    __shared__ double red[4][64];
    red[part][d] = s;
    __syncthreads();
    if (tid < 64)
        g_pool[((size_t)b * 16 + seg) * DM + tid] =
            red[0][tid] + red[1][tid] + red[2][tid] + red[3][tid];
}

// ================= K7b: combine + classifier =================
__global__ void k_pool_cls(const float* __restrict__ cW,
                           const float* __restrict__ cb,
                           float* __restrict__ out) {
    const int b = blockIdx.x;
    const int tid = threadIdx.x;   // 64
    __shared__ double pooled[64];
    double s = 0.0;
    for (int seg = 0; seg < 16; seg++)
        s += g_pool[((size_t)b * 16 + seg) * DM + tid];
    pooled[tid] = s / (double)L_;
    __syncthreads();
    if (tid < OUT_) {
        double acc = (double)cb[tid];
        for (int dd = 0; dd < DM; dd++)
            acc += pooled[dd] * (double)cW[dd * OUT_ + tid];
        out[b * OUT_ + tid] = (float)acc;
    }
}

// ================= launch =================
extern "C" void kernel_launch(void* const* d_in, const int* in_sizes, int n_in,
                              void* d_out, int out_size) {
    const float* x        = (const float*)d_in[0];
    const float* W_in     = (const float*)d_in[1];
    const float* b_in     = (const float*)d_in[2];
    const float* in_proj_W= (const float*)d_in[3];
    const float* in_proj_b= (const float*)d_in[4];
    const float* A_log    = (const float*)d_in[5];
    const float* Dp       = (const float*)d_in[6];
    const float* dt_bias  = (const float*)d_in[7];
    const float* out_proj_W = (const float*)d_in[8];
    const float* out_proj_b = (const float*)d_in[9];
    const float* cls_W    = (const float*)d_in[10];
    const float* cls_b    = (const float*)d_in[11];
    float* out = (float*)d_out;

    cudaFuncSetAttribute(k_inproj_mma, cudaFuncAttributeMaxDynamicSharedMemorySize, IP_SMEM);
    cudaFuncSetAttribute(k_outproj_mma, cudaFuncAttributeMaxDynamicSharedMemorySize, OP_SMEM);
    cudaFuncSetAttribute(k_chunk_output_mma, cudaFuncAttributeMaxDynamicSharedMemorySize, CO_SMEM);

    k_linear_in<<<BL / 16, 256>>>(x, W_in, b_in);
    for (int l = 0; l < NL; l++) {
        k_inproj_mma<<<BL / IPM, 256, IP_SMEM>>>(in_proj_W, in_proj_b, dt_bias, l);
        k_chunk_summary<<<B_ * NH * NCH, 256>>>(A_log, l);
        k_scan_seg<<<B_ * NH * NSEG, 1024>>>();
        k_scan_top<<<B_ * NH, 1024>>>();
        k_chunk_output_mma<<<B_ * NH * NCH, 256, CO_SMEM>>>(Dp, l);
        k_outproj_mma<<<BL / OPM, 256, OP_SMEM>>>(out_proj_W, out_proj_b, l);
    }
    k_pool_a<<<B_ * 16, 256>>>();
    k_pool_cls<<<B_, 64>>>(cls_W, cls_b, out);
}

// round 11
// speedup vs baseline: 1.2611x; 1.2611x over previous
#include <cuda_runtime.h>
#include <cuda_bf16.h>
#include <cstdint>

// ---------------- problem constants ----------------
#define B_     16
#define L_     8192
#define IN_    57
#define DM     64
#define DS     32
#define HD     32
#define NH     4
#define DI     128          // EXP*DM
#define DPROJ  324          // 2*DI + 2*DS + NH
#define NL     2
#define OUT_   6
#define Q      64           // chunk length
#define NCH    (L_ / Q)     // 128 chunks
#define NSEG   16           // scan segments
#define CPS    (NCH / NSEG) // 8 chunks per segment
#define BL     (B_ * L_)    // 131072 rows

// ---------------- scratch (device globals; allocation-free) ----------------
__device__ float g_h [BL * DM];
__device__ float g_X [BL * DI];
__device__ float g_Z [BL * DI];
__device__ float g_y [BL * DI];
__device__ float g_Bm[BL * DS];
__device__ float g_Cm[BL * DS];
__device__ float g_dt[BL * NH];
__device__ float g_la[BL * NH];
__device__ float g_Sd[B_ * NH * NCH * HD * DS];    // chunk delta states
__device__ float g_h0[B_ * NH * NCH * HD * DS];    // segment-local entry states
__device__ float g_aQ[B_ * NH * NCH];              // chunk total decay
__device__ float g_segS[B_ * NH * NSEG * HD * DS]; // segment delta states
__device__ float g_segA[B_ * NH * NSEG];           // segment decay product
__device__ float g_segIn[B_ * NH * NSEG * HD * DS];// segment entry states
__device__ double g_pool[B_ * 16 * DM];

// ---------------- helpers ----------------
__device__ __forceinline__ float siluf(float v) { return v / (1.f + __expf(-v)); }
__device__ __forceinline__ float softplusf(float v) { return (v > 20.f) ? v : log1pf(__expf(v)); }

__device__ __forceinline__ unsigned cvt_tf32(float f) {
    unsigned u; asm("cvt.rna.tf32.f32 %0, %1;" : "=r"(u) : "f"(f)); return u;
}
__device__ __forceinline__ void sp32(float v, unsigned& h, unsigned& l) {
    h = cvt_tf32(v);
    l = cvt_tf32(v - __uint_as_float(h));
}
__device__ __forceinline__ void mma_tf32(float* d, const unsigned* a, const unsigned* b) {
    asm volatile("mma.sync.aligned.m16n8k8.row.col.f32.tf32.tf32.f32 "
                 "{%0,%1,%2,%3},{%4,%5,%6,%7},{%8,%9},{%0,%1,%2,%3};"
                 : "+f"(d[0]), "+f"(d[1]), "+f"(d[2]), "+f"(d[3])
                 : "r"(a[0]), "r"(a[1]), "r"(a[2]), "r"(a[3]),
                   "r"(b[0]), "r"(b[1]));
}

// ================= K1: linear_in  h = x @ W_in + b_in =================
__global__ void k_linear_in(const float* __restrict__ x,
                            const float* __restrict__ W,
                            const float* __restrict__ bias) {
    const int row0 = blockIdx.x * 16;
    __shared__ float sx[16][IN_ + 1];
    const int tid = threadIdx.x;
    for (int idx = tid; idx < 16 * IN_; idx += 256) {
        int r = idx / IN_, k = idx % IN_;
        sx[r][k] = x[(size_t)(row0 + r) * IN_ + k];
    }
    __syncthreads();
    const int c = tid & 63, q = tid >> 6;
    float bc = bias[c];
    float acc[4] = {bc, bc, bc, bc};
    for (int k = 0; k < IN_; k++) {
        float wv = __ldg(&W[k * DM + c]);
#pragma unroll
        for (int j = 0; j < 4; j++) acc[j] += sx[q * 4 + j][k] * wv;
    }
#pragma unroll
    for (int j = 0; j < 4; j++)
        g_h[(size_t)(row0 + q * 4 + j) * DM + c] = acc[j];
}

// ================= K2: in_proj via tf32 MMA (3xTF32 split) =================
#define IPM 128
#define SH_STRIDE 68     // ≡4 mod 32: A-operand conflict-free
#define SW_STRIDE 72     // ≡8 mod 32: B-operand conflict-free
#define IP_SMEM ((IPM * SH_STRIDE + 64 * SW_STRIDE + 384) * 4)

__device__ __forceinline__ void ip_store(int row, int c, float v0, float v1,
                                         const float* __restrict__ dtb) {
    size_t r = (size_t)row;
    if (c < DI) {
        *reinterpret_cast<float2*>(&g_Z[r * DI + c]) = make_float2(siluf(v0), siluf(v1));
    } else if (c < 2 * DI) {
        *reinterpret_cast<float2*>(&g_X[r * DI + (c - DI)]) = make_float2(siluf(v0), siluf(v1));
    } else if (c < 2 * DI + DS) {
        *reinterpret_cast<float2*>(&g_Bm[r * DS + (c - 2 * DI)]) = make_float2(siluf(v0), siluf(v1));
    } else if (c < 2 * DI + 2 * DS) {
        *reinterpret_cast<float2*>(&g_Cm[r * DS + (c - 2 * DI - DS)]) = make_float2(siluf(v0), siluf(v1));
    } else {
        int hh = c - (2 * DI + 2 * DS);
        *reinterpret_cast<float2*>(&g_dt[r * NH + hh]) =
            make_float2(softplusf(v0 + __ldg(&dtb[hh])), softplusf(v1 + __ldg(&dtb[hh + 1])));
    }
}

__global__ void k_inproj_mma(const float* __restrict__ W,
                             const float* __restrict__ bias,
                             const float* __restrict__ dt_bias,
                             int l) {
    extern __shared__ float smem[];
    float* sH = smem;
    float* sW = sH + IPM * SH_STRIDE;
    float* sBias = sW + 64 * SW_STRIDE;

    const int row0 = blockIdx.x * IPM;
    const int tid = threadIdx.x;
    const int w = tid >> 5, lane = tid & 31;
    const int g = lane >> 2, tq = lane & 3;
    const float* Wl = W + (size_t)l * DM * DPROJ;
    const float* dtb = dt_bias + l * NH;

    for (int idx = tid; idx < IPM * DM; idx += 256) {
        int r = idx >> 6, k = idx & 63;
        sH[r * SH_STRIDE + k] = g_h[(size_t)(row0 + r) * DM + k];
    }
    for (int idx = tid; idx < 384; idx += 256)
        sBias[idx] = (idx < DPROJ) ? bias[l * DPROJ + idx] : 0.f;
    __syncthreads();

    const int rA0 = (w * 16 + g) * SH_STRIDE;
    const int rA1 = (w * 16 + g + 8) * SH_STRIDE;

    for (int chunk = 0; chunk < 6; chunk++) {
        for (int idx = tid; idx < 64 * 64; idx += 256) {
            int k = idx >> 6, n = idx & 63;
            int c = chunk * 64 + n;
            sW[k * SW_STRIDE + n] = (c < DPROJ) ? __ldg(&Wl[(size_t)k * DPROJ + c]) : 0.f;
        }
        __syncthreads();

        float fa[8][4];
#pragma unroll
        for (int nt = 0; nt < 8; nt++)
#pragma unroll
            for (int j = 0; j < 4; j++) fa[nt][j] = 0.f;

#pragma unroll
        for (int k0 = 0; k0 < 64; k0 += 8) {
            unsigned ahi[4], alo[4];
            sp32(sH[rA0 + k0 + tq],     ahi[0], alo[0]);
            sp32(sH[rA1 + k0 + tq],     ahi[1], alo[1]);
            sp32(sH[rA0 + k0 + tq + 4], ahi[2], alo[2]);
            sp32(sH[rA1 + k0 + tq + 4], ahi[3], alo[3]);
#pragma unroll
            for (int nt = 0; nt < 8; nt++) {
                unsigned bhi[2], blo[2];
                sp32(sW[(k0 + tq) * SW_STRIDE + nt * 8 + g],     bhi[0], blo[0]);
                sp32(sW[(k0 + tq + 4) * SW_STRIDE + nt * 8 + g], bhi[1], blo[1]);
                mma_tf32(fa[nt], ahi, bhi);
                mma_tf32(fa[nt], ahi, blo);
                mma_tf32(fa[nt], alo, bhi);
            }
        }
        __syncthreads();

#pragma unroll
        for (int nt = 0; nt < 8; nt++) {
            int cg = chunk * 64 + nt * 8 + 2 * tq;
            if (cg >= DPROJ) continue;
            float b0v = sBias[cg], b1v = sBias[cg + 1];
            int r0 = row0 + w * 16 + g;
            ip_store(r0,     cg, fa[nt][0] + b0v, fa[nt][1] + b1v, dtb);
            ip_store(r0 + 8, cg, fa[nt][2] + b0v, fa[nt][3] + b1v, dtb);
        }
    }
}

// ================= K3: per-chunk summary via tf32 MMA =================
// Sd[p][n] = sum_s X[s][p] * (w_s * B[s][n]);  M=32(p), N=32(n), K=64(s)
#define XT_ST 68   // sXT [32][68]  A-operand, ≡4 mod 32
#define BW_ST 40   // sBw [64][40]  B-operand, ≡8 mod 32
__global__ void k_chunk_summary(const float* __restrict__ A_log, int l) {
    const int bx = blockIdx.x;
    const int ch = bx & (NCH - 1);
    const int h  = (bx >> 7) & 3;
    const int b  = bx >> 9;
    const size_t base = (size_t)b * L_ + (size_t)ch * Q;
    __shared__ float sXT[HD * XT_ST];    // X^T[p][s]
    __shared__ float sBw[Q * BW_ST];     // w_s * B[s][n]
    __shared__ float sla[Q], sw_[Q], sdt[Q];
    const int tid = threadIdx.x;               // 256 threads
    const int w = tid >> 5, lane = tid & 31;
    const int g = lane >> 2, tq = lane & 3;

    for (int idx = tid; idx < Q * 32; idx += 256) {
        int s = idx >> 5, j = idx & 31;
        sXT[j * XT_ST + s] = g_X [(base + s) * DI + h * HD + j];
        sBw[s * BW_ST + j] = g_Bm[(base + s) * DS + j];
    }
    if (tid < Q) sdt[tid] = g_dt[(base + tid) * NH + h];
    __syncthreads();

    const float A = -expf(A_log[l * NH + h]);
    if (tid < Q) {
        float v = sdt[tid] * A;
#pragma unroll
        for (int o = 1; o < 32; o <<= 1) {
            float u = __shfl_up_sync(0xffffffffu, v, o);
            if ((tid & 31) >= o) v += u;
        }
        sla[tid] = v;
    }
    __syncthreads();
    if (tid >= 32 && tid < 64) sla[tid] += sla[31];
    __syncthreads();
    const float laQ = sla[Q - 1];
    if (tid < Q) {
        g_la[(base + tid) * NH + h] = sla[tid];
        sw_[tid] = sdt[tid] * __expf(laQ - sla[tid]);
    }
    __syncthreads();
    for (int idx = tid; idx < Q * HD; idx += 256) {
        int s = idx >> 5;
        sBw[s * BW_ST + (idx & 31)] *= sw_[s];
    }
    __syncthreads();

    // 8 warps = 2 m-stripes x 4 n-groups; each warp m16n8k64
    const int mrow = (w & 1) * 16;
    const int ng = w >> 1;
    const int rA0 = (mrow + g) * XT_ST;
    const int rA1 = (mrow + g + 8) * XT_ST;
    float fa[4] = {0.f, 0.f, 0.f, 0.f};
#pragma unroll
    for (int k0 = 0; k0 < Q; k0 += 8) {
        unsigned ahi[4], alo[4];
        sp32(sXT[rA0 + k0 + tq],     ahi[0], alo[0]);
        sp32(sXT[rA1 + k0 + tq],     ahi[1], alo[1]);
        sp32(sXT[rA0 + k0 + tq + 4], ahi[2], alo[2]);
        sp32(sXT[rA1 + k0 + tq + 4], ahi[3], alo[3]);
        unsigned bhi[2], blo[2];
        sp32(sBw[(k0 + tq) * BW_ST + ng * 8 + g],     bhi[0], blo[0]);
        sp32(sBw[(k0 + tq + 4) * BW_ST + ng * 8 + g], bhi[1], blo[1]);
        mma_tf32(fa, ahi, bhi);
        mma_tf32(fa, ahi, blo);
        mma_tf32(fa, alo, bhi);
    }

    float* dst = &g_Sd[(size_t)bx * 1024];
    const int n0 = ng * 8 + 2 * tq;
    const int p0 = mrow + g;
    *reinterpret_cast<float2*>(&dst[p0 * 32 + n0])       = make_float2(fa[0], fa[1]);
    *reinterpret_cast<float2*>(&dst[(p0 + 8) * 32 + n0]) = make_float2(fa[2], fa[3]);
    if (tid == 0) g_aQ[bx] = __expf(laQ);
}

// ================= K4a: segment-local scan =================
__global__ void k_scan_seg() {
    const int blk = blockIdx.x;
    const int bh = blk >> 4, seg = blk & (NSEG - 1);
    const int tid = threadIdx.x;       // 1024
    const size_t cbase = (size_t)bh * NCH + seg * CPS;
    float hloc = 0.f;
#pragma unroll
    for (int j = 0; j < CPS; j++) {
        size_t o = (cbase + j) * 1024 + tid;
        g_h0[o] = hloc;
        hloc = __ldg(&g_aQ[cbase + j]) * hloc + g_Sd[o];
    }
    g_segS[(size_t)blk * 1024 + tid] = hloc;
    if (tid == 0) {
        float p = 1.f;
#pragma unroll
        for (int j = 0; j < CPS; j++) p *= g_aQ[cbase + j];
        g_segA[blk] = p;
    }
}

// ================= K4b: top-level segment scan =================
__global__ void k_scan_top() {
    const int bh = blockIdx.x;         // 64 blocks
    const int tid = threadIdx.x;       // 1024
    float carry = 0.f;
#pragma unroll
    for (int seg = 0; seg < NSEG; seg++) {
        size_t o = ((size_t)bh * NSEG + seg) * 1024 + tid;
        g_segIn[o] = carry;
        carry = __ldg(&g_segA[bh * NSEG + seg]) * carry + g_segS[o];
    }
}

// ================= K5: chunk output via tf32 MMA =================
#define SXO 40   // ≡8 mod 32
#define SBC 36   // ≡4 mod 32
#define SGS 68   // ≡4 mod 32
#define CO_SMEM ((Q*SXO + Q*SBC + Q*SBC + HD*SBC + Q*SGS + 3*Q) * 4)

__global__ void k_chunk_output_mma(const float* __restrict__ Dp, int l) {
    extern __shared__ float sm[];
    float* sX  = sm;                     // [64][SXO]
    float* sB  = sX + Q * SXO;           // [64][SBC]
    float* sC  = sB + Q * SBC;           // [64][SBC]  (becomes Ce in-place)
    float* sh0 = sC + Q * SBC;           // [32][SBC]
    float* sG  = sh0 + HD * SBC;         // [64][SGS]
    float* sla = sG + Q * SGS;           // [64]
    float* sdt = sla + Q;                // [64]
    float* sE  = sdt + Q;                // [64] exp(la_t)
    __shared__ float sprefA;

    const int bx = blockIdx.x;
    const int ch = bx & (NCH - 1);
    const int h  = (bx >> 7) & 3;
    const int b  = bx >> 9;
    const int bhIdx = b * NH + h;
    const size_t base = (size_t)b * L_ + (size_t)ch * Q;
    const int tid = threadIdx.x;         // 256
    const int w = tid >> 5, lane = tid & 31;
    const int g = lane >> 2, tq = lane & 3;
    const int mrow = (w & 3) * 16;       // M stripe (t rows)

    if (tid == 0) {
        float p = 1.f;
        int j0 = ch & (CPS - 1);
        size_t cb = (size_t)bhIdx * NCH + (size_t)(ch & ~(CPS - 1));
        for (int j = 0; j < j0; j++) p *= g_aQ[cb + j];
        sprefA = p;
    }
    for (int idx = tid; idx < Q * 32; idx += 256) {
        int s = idx >> 5, j = idx & 31;
        sX[s * SXO + j] = g_X [(base + s) * DI + h * HD + j];
        sB[s * SBC + j] = g_Bm[(base + s) * DS + j];
        sC[s * SBC + j] = g_Cm[(base + s) * DS + j];
    }
    if (tid < Q) {
        float la = g_la[(base + tid) * NH + h];
        sla[tid] = la;
        sdt[tid] = g_dt[(base + tid) * NH + h];
        sE[tid] = __expf(la);
    }
    __syncthreads();

    // combined entry state into sh0[p][n]
    {
        const float pa = sprefA;
        const int seg = ch >> 3;
        const size_t sio = ((size_t)bhIdx * NSEG + seg) * 1024;
        for (int idx = tid; idx < 1024; idx += 256)
            sh0[(idx >> 5) * SBC + (idx & 31)] =
                g_h0[(size_t)bx * 1024 + idx] + pa * g_segIn[sio + idx];
    }
    __syncthreads();

    // ---- Phase 1: G = C . B^T  (M=64 t, N=64 s, K=32 n) ----
    const int shalf = (w >> 2) * 32;
    float ga[4][4];
#pragma unroll
    for (int nt = 0; nt < 4; nt++)
#pragma unroll
        for (int j = 0; j < 4; j++) ga[nt][j] = 0.f;

#pragma unroll
    for (int k0 = 0; k0 < 32; k0 += 8) {
        unsigned ahi[4], alo[4];
        sp32(sC[(mrow + g) * SBC + k0 + tq],         ahi[0], alo[0]);
        sp32(sC[(mrow + g + 8) * SBC + k0 + tq],     ahi[1], alo[1]);
        sp32(sC[(mrow + g) * SBC + k0 + tq + 4],     ahi[2], alo[2]);
        sp32(sC[(mrow + g + 8) * SBC + k0 + tq + 4], ahi[3], alo[3]);
#pragma unroll
        for (int nt = 0; nt < 4; nt++) {
            int sc = shalf + nt * 8 + g;
            unsigned bhi[2], blo[2];
            sp32(sB[sc * SBC + k0 + tq],     bhi[0], blo[0]);
            sp32(sB[sc * SBC + k0 + tq + 4], bhi[1], blo[1]);
            mma_tf32(ga[nt], ahi, bhi);
            mma_tf32(ga[nt], ahi, blo);
            mma_tf32(ga[nt], alo, bhi);
        }
    }
    __syncthreads();   // everyone done reading sC/sB in MMA

    // ---- Phase 2: mask+exp G into sG; scale sC -> Ce in place ----
#pragma unroll
    for (int nt = 0; nt < 4; nt++) {
        int s0 = shalf + nt * 8 + 2 * tq;
        int t0 = mrow + g, t1 = mrow + g + 8;
        float la0 = sla[t0], la1 = sla[t1];
        float d0 = sdt[s0], d1 = sdt[s0 + 1];
        float ls0 = sla[s0], ls1 = sla[s0 + 1];
        sG[t0 * SGS + s0]     = (s0 <= t0)     ? ga[nt][0] * d0 * __expf(la0 - ls0) : 0.f;
        sG[t0 * SGS + s0 + 1] = (s0 + 1 <= t0) ? ga[nt][1] * d1 * __expf(la0 - ls1) : 0.f;
        sG[t1 * SGS + s0]     = (s0 <= t1)     ? ga[nt][2] * d0 * __expf(la1 - ls0) : 0.f;
        sG[t1 * SGS + s0 + 1] = (s0 + 1 <= t1) ? ga[nt][3] * d1 * __expf(la1 - ls1) : 0.f;
    }
    for (int idx = tid; idx < Q * 32; idx += 256) {
        int t = idx >> 5;
        sC[t * SBC + (idx & 31)] *= sE[t];
    }
    __syncthreads();

    // ---- Phase 3: Y = G.X (k=64) + Ce.h0^T (k=32); M=64 t, N=32 p ----
    const int phalf = (w >> 2) * 16;
    float fa[2][4];
#pragma unroll
    for (int nt = 0; nt < 2; nt++)
#pragma unroll
        for (int j = 0; j < 4; j++) fa[nt][j] = 0.f;

#pragma unroll
    for (int k0 = 0; k0 < Q; k0 += 8) {
        unsigned ahi[4], alo[4];
        sp32(sG[(mrow + g) * SGS + k0 + tq],         ahi[0], alo[0]);
        sp32(sG[(mrow + g + 8) * SGS + k0 + tq],     ahi[1], alo[1]);
        sp32(sG[(mrow + g) * SGS + k0 + tq + 4],     ahi[2], alo[2]);
        sp32(sG[(mrow + g + 8) * SGS + k0 + tq + 4], ahi[3], alo[3]);
#pragma unroll
        for (int nt = 0; nt < 2; nt++) {
            int pc = phalf + nt * 8 + g;
            unsigned bhi[2], blo[2];
            sp32(sX[(k0 + tq) * SXO + pc],     bhi[0], blo[0]);
            sp32(sX[(k0 + tq + 4) * SXO + pc], bhi[1], blo[1]);
            mma_tf32(fa[nt], ahi, bhi);
            mma_tf32(fa[nt], ahi, blo);
            mma_tf32(fa[nt], alo, bhi);
        }
    }
#pragma unroll
    for (int k0 = 0; k0 < 32; k0 += 8) {
        unsigned ahi[4], alo[4];
        sp32(sC[(mrow + g) * SBC + k0 + tq],         ahi[0], alo[0]);
        sp32(sC[(mrow + g + 8) * SBC + k0 + tq],     ahi[1], alo[1]);
        sp32(sC[(mrow + g) * SBC + k0 + tq + 4],     ahi[2], alo[2]);
        sp32(sC[(mrow + g + 8) * SBC + k0 + tq + 4], ahi[3], alo[3]);
#pragma unroll
        for (int nt = 0; nt < 2; nt++) {
            int pc = phalf + nt * 8 + g;
            unsigned bhi[2], blo[2];
            sp32(sh0[pc * SBC + k0 + tq],     bhi[0], blo[0]);
            sp32(sh0[pc * SBC + k0 + tq + 4], bhi[1], blo[1]);
            mma_tf32(fa[nt], ahi, bhi);
            mma_tf32(fa[nt], ahi, blo);
            mma_tf32(fa[nt], alo, bhi);
        }
    }

    // ---- Epilogue: D-skip + z-gate, store ----
    const float Dh = Dp[l * NH + h];
#pragma unroll
    for (int nt = 0; nt < 2; nt++) {
        int pc = phalf + nt * 8 + 2 * tq;
#pragma unroll
        for (int half = 0; half < 2; half++) {
            int t = mrow + g + half * 8;
            size_t o = (base + t) * DI + h * HD + pc;
            float x0 = sX[t * SXO + pc], x1 = sX[t * SXO + pc + 1];
            float2 z = *reinterpret_cast<const float2*>(&g_Z[o]);
            float2 r;
            r.x = (fa[nt][half * 2 + 0] + Dh * x0) * z.x;
            r.y = (fa[nt][half * 2 + 1] + Dh * x1) * z.y;
            *reinterpret_cast<float2*>(&g_y[o]) = r;
        }
    }
}

// ================= K6: out_proj via tf32 MMA + residual =================
#define OPM 128
#define SY_STRIDE 132    // ≡4 mod 32
#define OP_SMEM ((OPM * SY_STRIDE + DI * SW_STRIDE + 64) * 4)
__global__ void k_outproj_mma(const float* __restrict__ Wo,
                              const float* __restrict__ bo,
                              int l) {
    extern __shared__ float smem[];
    float* sY = smem;
    float* sW2 = sY + OPM * SY_STRIDE;
    float* sB2 = sW2 + DI * SW_STRIDE;

    const int row0 = blockIdx.x * OPM;
    const int tid = threadIdx.x;
    const int w = tid >> 5, lane = tid & 31;
    const int g = lane >> 2, tq = lane & 3;
    const float* Wl = Wo + (size_t)l * DI * DM;

    for (int idx = tid; idx < OPM * DI; idx += 256) {
        int r = idx >> 7, k = idx & 127;
        sY[r * SY_STRIDE + k] = g_y[(size_t)(row0 + r) * DI + k];
    }
    for (int idx = tid; idx < DI * DM; idx += 256) {
        int k = idx >> 6, n = idx & 63;
        sW2[k * SW_STRIDE + n] = __ldg(&Wl[(size_t)k * DM + n]);
    }
    if (tid < 64) sB2[tid] = bo[l * DM + tid];
    __syncthreads();

    const int rA0 = (w * 16 + g) * SY_STRIDE;
    const int rA1 = (w * 16 + g + 8) * SY_STRIDE;

    float fa[8][4];
#pragma unroll
    for (int nt = 0; nt < 8; nt++)
#pragma unroll
        for (int j = 0; j < 4; j++) fa[nt][j] = 0.f;

#pragma unroll 4
    for (int k0 = 0; k0 < DI; k0 += 8) {
        unsigned ahi[4], alo[4];
        sp32(sY[rA0 + k0 + tq],     ahi[0], alo[0]);
        sp32(sY[rA1 + k0 + tq],     ahi[1], alo[1]);
        sp32(sY[rA0 + k0 + tq + 4], ahi[2], alo[2]);
        sp32(sY[rA1 + k0 + tq + 4], ahi[3], alo[3]);
#pragma unroll
        for (int nt = 0; nt < 8; nt++) {
            unsigned bhi[2], blo[2];
            sp32(sW2[(k0 + tq) * SW_STRIDE + nt * 8 + g],     bhi[0], blo[0]);
            sp32(sW2[(k0 + tq + 4) * SW_STRIDE + nt * 8 + g], bhi[1], blo[1]);
            mma_tf32(fa[nt], ahi, bhi);
            mma_tf32(fa[nt], ahi, blo);
            mma_tf32(fa[nt], alo, bhi);
        }
    }

#pragma unroll
    for (int nt = 0; nt < 8; nt++) {
        int c = nt * 8 + 2 * tq;
        float bc0 = sB2[c], bc1 = sB2[c + 1];
        int r0 = row0 + w * 16 + g;
#pragma unroll
        for (int half = 0; half < 2; half++) {
            int r = r0 + half * 8;
            size_t o = (size_t)r * DM + c;
            float2 hv = *reinterpret_cast<float2*>(&g_h[o]);
            hv.x += fa[nt][half * 2 + 0] + bc0;
            hv.y += fa[nt][half * 2 + 1] + bc1;
            *reinterpret_cast<float2*>(&g_h[o]) = hv;
        }
    }
}

// ================= K7a: pooling partial sums =================
__global__ void k_pool_a() {
    const int b = blockIdx.x >> 4, seg = blockIdx.x & 15;
    const int tid = threadIdx.x;   // 256
    const int d = tid & 63, part = tid >> 6;
    double s = 0.0;
    for (int ll = seg * 512 + part; ll < (seg + 1) * 512; ll += 4)
        s += (double)g_h[((size_t)b * L_ + ll) * DM + d];
    __shared__ double red[4][64];
    red[part][d] = s;
    __syncthreads();
    if (tid < 64)
        g_pool[((size_t)b * 16 + seg) * DM + tid] =
            red[0][tid] + red[1][tid] + red[2][tid] + red[3][tid];
}

// ================= K7b: combine + classifier =================
__global__ void k_pool_cls(const float* __restrict__ cW,
                           const float* __restrict__ cb,
                           float* __restrict__ out) {
    const int b = blockIdx.x;
    const int tid = threadIdx.x;   // 64
    __shared__ double pooled[64];
    double s = 0.0;
    for (int seg = 0; seg < 16; seg++)
        s += g_pool[((size_t)b * 16 + seg) * DM + tid];
    pooled[tid] = s / (double)L_;
    __syncthreads();
    if (tid < OUT_) {
        double acc = (double)cb[tid];
        for (int dd = 0; dd < DM; dd++)
            acc += pooled[dd] * (double)cW[dd * OUT_ + tid];
        out[b * OUT_ + tid] = (float)acc;
    }
}

// ================= launch =================
extern "C" void kernel_launch(void* const* d_in, const int* in_sizes, int n_in,
                              void* d_out, int out_size) {
    const float* x        = (const float*)d_in[0];
    const float* W_in     = (const float*)d_in[1];
    const float* b_in     = (const float*)d_in[2];
    const float* in_proj_W= (const float*)d_in[3];
    const float* in_proj_b= (const float*)d_in[4];
    const float* A_log    = (const float*)d_in[5];
    const float* Dp       = (const float*)d_in[6];
    const float* dt_bias  = (const float*)d_in[7];
    const float* out_proj_W = (const float*)d_in[8];
    const float* out_proj_b = (const float*)d_in[9];
    const float* cls_W    = (const float*)d_in[10];
    const float* cls_b    = (const float*)d_in[11];
    float* out = (float*)d_out;

    cudaFuncSetAttribute(k_inproj_mma, cudaFuncAttributeMaxDynamicSharedMemorySize, IP_SMEM);
    cudaFuncSetAttribute(k_outproj_mma, cudaFuncAttributeMaxDynamicSharedMemorySize, OP_SMEM);
    cudaFuncSetAttribute(k_chunk_output_mma, cudaFuncAttributeMaxDynamicSharedMemorySize, CO_SMEM);

    k_linear_in<<<BL / 16, 256>>>(x, W_in, b_in);
    for (int l = 0; l < NL; l++) {
        k_inproj_mma<<<BL / IPM, 256, IP_SMEM>>>(in_proj_W, in_proj_b, dt_bias, l);
        k_chunk_summary<<<B_ * NH * NCH, 256>>>(A_log, l);
        k_scan_seg<<<B_ * NH * NSEG, 1024>>>();
        k_scan_top<<<B_ * NH, 1024>>>();
        k_chunk_output_mma<<<B_ * NH * NCH, 256, CO_SMEM>>>(Dp, l);
        k_outproj_mma<<<BL / OPM, 256, OP_SMEM>>>(out_proj_W, out_proj_b, l);
    }
    k_pool_a<<<B_ * 16, 256>>>();
    k_pool_cls<<<B_, 64>>>(cls_W, cls_b, out);
}